// round 7
// baseline (speedup 1.0000x reference)
#include <cuda_runtime.h>
#include <cuda_bf16.h>
#include <cstdint>

// ---------------------------------------------------------------- shapes
#define D_FEAT 4096
#define N_SAMP 8192
#define OUT_D  2048

// ---------------------------------------------------------------- scratch
__device__ __nv_bfloat16 g_psi_hi[(size_t)OUT_D * N_SAMP];
__device__ __nv_bfloat16 g_psi_lo[(size_t)OUT_D * N_SAMP];
__device__ __nv_bfloat16 g_x_hi[(size_t)D_FEAT * N_SAMP];
__device__ __nv_bfloat16 g_x_lo[(size_t)D_FEAT * N_SAMP];
__device__ __nv_bfloat16 g_tmp_hi[(size_t)OUT_D * D_FEAT];
__device__ __nv_bfloat16 g_tmp_lo[(size_t)OUT_D * D_FEAT];
__device__ float g_part1[(size_t)4 * OUT_D * D_FEAT];
__device__ float g_part2[(size_t)2 * OUT_D * N_SAMP];

// ---------------------------------------------------------------- helpers
__device__ __forceinline__ uint32_t smem_u32(const void* p) {
    uint32_t a;
    asm("{ .reg .u64 t; cvta.to.shared.u64 t, %1; cvt.u32.u64 %0, t; }" : "=r"(a) : "l"(p));
    return a;
}
__device__ __forceinline__ void cpasync16(uint32_t s, const void* g) {
    asm volatile("cp.async.cg.shared.global [%0], [%1], 16;" :: "r"(s), "l"(g));
}
__device__ __forceinline__ void cp_commit() {
    asm volatile("cp.async.commit_group;" ::: "memory");
}
__device__ __forceinline__ void cp_wait1() {
    asm volatile("cp.async.wait_group 1;" ::: "memory");
}
__device__ __forceinline__ void ldsm4(uint32_t* r, uint32_t addr) {
    asm volatile("ldmatrix.sync.aligned.m8n8.x4.shared.b16 {%0,%1,%2,%3}, [%4];"
                 : "=r"(r[0]), "=r"(r[1]), "=r"(r[2]), "=r"(r[3]) : "r"(addr));
}
__device__ __forceinline__ void ldsm4t(uint32_t* r, uint32_t addr) {
    asm volatile("ldmatrix.sync.aligned.m8n8.x4.trans.shared.b16 {%0,%1,%2,%3}, [%4];"
                 : "=r"(r[0]), "=r"(r[1]), "=r"(r[2]), "=r"(r[3]) : "r"(addr));
}
__device__ __forceinline__ void mma16816(float* c, const uint32_t* a, const uint32_t* b) {
    asm volatile("mma.sync.aligned.m16n8k16.row.col.f32.bf16.bf16.f32 "
                 "{%0,%1,%2,%3}, {%4,%5,%6,%7}, {%8,%9}, {%0,%1,%2,%3};"
                 : "+f"(c[0]), "+f"(c[1]), "+f"(c[2]), "+f"(c[3])
                 : "r"(a[0]), "r"(a[1]), "r"(a[2]), "r"(a[3]), "r"(b[0]), "r"(b[1]));
}
__device__ __forceinline__ void split_f32(float v, __nv_bfloat16& h, __nv_bfloat16& l) {
    h = __float2bfloat16(v);
    l = __float2bfloat16(v - __bfloat162float(h));
}
__device__ __forceinline__ uint32_t sw64(uint32_t off) {
    return off ^ ((off >> 3) & 0x30);
}
__device__ __forceinline__ uint32_t sw128(uint32_t off) {
    return off ^ ((off >> 3) & 0x70);
}

// ------------------------------------------------- fused prep
#define XCHUNKS ((D_FEAT * (N_SAMP / 4)) / 256)

__global__ void prep_kernel(const float* __restrict__ Psi, const float* __restrict__ x,
                            __nv_bfloat16* __restrict__ phi, __nv_bfloat16* __restrict__ plo,
                            __nv_bfloat16* __restrict__ xh, __nv_bfloat16* __restrict__ xl) {
    if (blockIdx.x < OUT_D) {
        const int row = blockIdx.x;
        const float4* p = reinterpret_cast<const float4*>(Psi) + (size_t)row * (N_SAMP / 4);
        float4 v[8];
        float s = 0.f;
        #pragma unroll
        for (int q = 0; q < 8; ++q) {
            v[q] = p[q * 256 + threadIdx.x];
            s += (v[q].x + v[q].y) + (v[q].z + v[q].w);
        }
        __shared__ float red[256];
        red[threadIdx.x] = s;
        __syncthreads();
        #pragma unroll
        for (int off = 128; off > 0; off >>= 1) {
            if (threadIdx.x < off) red[threadIdx.x] += red[threadIdx.x + off];
            __syncthreads();
        }
        const float m = red[0] * (1.0f / N_SAMP);
        ushort4* hp = reinterpret_cast<ushort4*>(phi) + (size_t)row * (N_SAMP / 4);
        ushort4* lp = reinterpret_cast<ushort4*>(plo) + (size_t)row * (N_SAMP / 4);
        #pragma unroll
        for (int q = 0; q < 8; ++q) {
            float4 w = v[q];
            w.x -= m; w.y -= m; w.z -= m; w.w -= m;
            __nv_bfloat16 h0, l0, h1, l1, h2, l2, h3, l3;
            split_f32(w.x, h0, l0); split_f32(w.y, h1, l1);
            split_f32(w.z, h2, l2); split_f32(w.w, h3, l3);
            hp[q * 256 + threadIdx.x] = make_ushort4(
                __bfloat16_as_ushort(h0), __bfloat16_as_ushort(h1),
                __bfloat16_as_ushort(h2), __bfloat16_as_ushort(h3));
            lp[q * 256 + threadIdx.x] = make_ushort4(
                __bfloat16_as_ushort(l0), __bfloat16_as_ushort(l1),
                __bfloat16_as_ushort(l2), __bfloat16_as_ushort(l3));
        }
    } else {
        const size_t i = (size_t)(blockIdx.x - OUT_D) * 256 + threadIdx.x;
        float4 v = reinterpret_cast<const float4*>(x)[i];
        __nv_bfloat16 h0, l0, h1, l1, h2, l2, h3, l3;
        split_f32(v.x, h0, l0); split_f32(v.y, h1, l1);
        split_f32(v.z, h2, l2); split_f32(v.w, h3, l3);
        reinterpret_cast<ushort4*>(xh)[i] = make_ushort4(
            __bfloat16_as_ushort(h0), __bfloat16_as_ushort(h1),
            __bfloat16_as_ushort(h2), __bfloat16_as_ushort(h3));
        reinterpret_cast<ushort4*>(xl)[i] = make_ushort4(
            __bfloat16_as_ushort(l0), __bfloat16_as_ushort(l1),
            __bfloat16_as_ushort(l2), __bfloat16_as_ushort(l3));
    }
}

// ---------------------------------------------------------------- HMMA GEMM (split-K)
#define STG_BYTES 32768
#define AH_OFF 0
#define AL_OFF 8192
#define BH_OFF 16384
#define BL_OFF 24576

template <int BTRANS>
__global__ void __launch_bounds__(256, 2)
gemm_hmma(const __nv_bfloat16* __restrict__ Ahi, const __nv_bfloat16* __restrict__ Alo,
          const __nv_bfloat16* __restrict__ Bhi, const __nv_bfloat16* __restrict__ Blo,
          float* __restrict__ Cpart,
          int N, int K, int klen, int ldb) {
    extern __shared__ char smem[];
    const uint32_t sb = smem_u32(smem);

    const int tid  = threadIdx.x;
    const int wid  = tid >> 5;
    const int lane = tid & 31;
    const int wm   = wid & 3;
    const int wn   = wid >> 2;
    const int m0   = blockIdx.x * 128;
    const int n0   = blockIdx.y * 128;
    const int kz   = blockIdx.z * klen;
    float* C = Cpart + (size_t)blockIdx.z * ((size_t)gridDim.x * 128) * N;

    // ---- loader setup (incremental global pointers)
    uint32_t soffA[2], soffB[2];
    const __nv_bfloat16 *pAh[2], *pAl[2], *pBh[2], *pBl[2];
    const size_t kstepA = 32;
    const size_t kstepB = BTRANS ? (size_t)32 * (size_t)ldb : (size_t)32;
    #pragma unroll
    for (int q = 0; q < 2; ++q) {
        const int id = q * 256 + tid;
        {
            const int r = id >> 2, sg = id & 3;
            soffA[q] = sw64((uint32_t)(r * 64 + sg * 16));
            const size_t g = (size_t)(m0 + r) * K + kz + sg * 8;
            pAh[q] = Ahi + g;
            pAl[q] = Alo + g;
        }
        if (BTRANS == 0) {
            const int r = id >> 2, sg = id & 3;
            soffB[q] = sw64((uint32_t)(r * 64 + sg * 16));
            const size_t g = (size_t)(n0 + r) * (size_t)ldb + kz + sg * 8;
            pBh[q] = Bhi + g;
            pBl[q] = Blo + g;
        } else {
            const int r = id >> 4, c = id & 15;
            const int sub = c >> 3;
            soffB[q] = sub * 4096 + sw128((uint32_t)(r * 128 + (c & 7) * 16));
            const size_t g = (size_t)(kz + r) * (size_t)ldb + n0 + c * 8;
            pBh[q] = Bhi + g;
            pBl[q] = Blo + g;
        }
    }

    auto load_stage = [&](int t) {
        const uint32_t base = sb + (t % 3) * STG_BYTES;
        #pragma unroll
        for (int q = 0; q < 2; ++q) {
            cpasync16(base + AH_OFF + soffA[q], pAh[q]);
            cpasync16(base + AL_OFF + soffA[q], pAl[q]);
            cpasync16(base + BH_OFF + soffB[q], pBh[q]);
            cpasync16(base + BL_OFF + soffB[q], pBl[q]);
            pAh[q] += kstepA; pAl[q] += kstepA;
            pBh[q] += kstepB; pBl[q] += kstepB;
        }
        cp_commit();
    };

    // ---- precomputed ldsm offsets (hoisted out of mainloop)
    const int quad = lane >> 3, l8 = lane & 7;
    const int a_row  = wm * 32 + (quad & 1) * 8 + l8;
    const int a_colq = (quad >> 1) * 8;
    uint32_t aoff[2][2];   // [h][i]
    uint32_t boff[2][4];   // [h][jj*2+j]
    #pragma unroll
    for (int h = 0; h < 2; ++h) {
        const int k0 = h * 16;
        #pragma unroll
        for (int i = 0; i < 2; ++i)
            aoff[h][i] = sw64((uint32_t)((a_row + i * 16) * 64 + (k0 + a_colq) * 2));
        #pragma unroll
        for (int jt = 0; jt < 4; ++jt) {
            if (BTRANS == 0) {
                const int b_row = wn * 64 + (quad >> 1) * 8 + l8 + jt * 16;
                const int b_col = (quad & 1) * 8;
                boff[h][jt] = sw64((uint32_t)(b_row * 64 + (k0 + b_col) * 2));
            } else {
                const int b_k   = k0 + (quad & 1) * 8 + l8;
                const int ncol  = wn * 64 + (quad >> 1) * 8 + jt * 16;
                const int sub   = ncol >> 6;
                boff[h][jt] = sub * 4096 + sw128((uint32_t)(b_k * 128 + (ncol & 63) * 2));
            }
        }
    }

    float acc[2][8][4];
    #pragma unroll
    for (int i = 0; i < 2; ++i)
        #pragma unroll
        for (int j = 0; j < 8; ++j)
            #pragma unroll
            for (int e = 0; e < 4; ++e) acc[i][j][e] = 0.f;

    const int ntiles = klen / 32;
    load_stage(0);
    load_stage(1);

    for (int s = 0; s < ntiles; ++s) {
        cp_wait1();
        __syncthreads();
        if (s + 2 < ntiles) load_stage(s + 2);

        const uint32_t st = sb + (s % 3) * STG_BYTES;
        #pragma unroll
        for (int h = 0; h < 2; ++h) {
            uint32_t Ah[2][4], Al[2][4];
            #pragma unroll
            for (int i = 0; i < 2; ++i) {
                ldsm4(Ah[i], st + AH_OFF + aoff[h][i]);
                ldsm4(Al[i], st + AL_OFF + aoff[h][i]);
            }
            #pragma unroll
            for (int jj = 0; jj < 2; ++jj) {
                uint32_t Bh[2][4], Bl[2][4];
                #pragma unroll
                for (int j = 0; j < 2; ++j) {
                    const uint32_t bo = boff[h][jj * 2 + j];
                    if (BTRANS == 0) {
                        ldsm4(Bh[j], st + BH_OFF + bo);
                        ldsm4(Bl[j], st + BL_OFF + bo);
                    } else {
                        ldsm4t(Bh[j], st + BH_OFF + bo);
                        ldsm4t(Bl[j], st + BL_OFF + bo);
                    }
                }
                // term-major: 8 independent MMAs between writes to same acc
                #pragma unroll
                for (int i = 0; i < 2; ++i)
                    #pragma unroll
                    for (int j = 0; j < 4; ++j)
                        mma16816(acc[i][jj * 4 + j], Ah[i], &Bh[j >> 1][(j & 1) * 2]);
                #pragma unroll
                for (int i = 0; i < 2; ++i)
                    #pragma unroll
                    for (int j = 0; j < 4; ++j)
                        mma16816(acc[i][jj * 4 + j], Ah[i], &Bl[j >> 1][(j & 1) * 2]);
                #pragma unroll
                for (int i = 0; i < 2; ++i)
                    #pragma unroll
                    for (int j = 0; j < 4; ++j)
                        mma16816(acc[i][jj * 4 + j], Al[i], &Bh[j >> 1][(j & 1) * 2]);
            }
        }
    }

    // ---- epilogue
    const int r_base = m0 + wm * 32 + (lane >> 2);
    const int c_base = n0 + wn * 64 + (lane & 3) * 2;
    #pragma unroll
    for (int i = 0; i < 2; ++i) {
        #pragma unroll
        for (int j = 0; j < 8; ++j) {
            const int r0 = r_base + i * 16;
            const int c  = c_base + j * 8;
            *reinterpret_cast<float2*>(C + (size_t)r0 * N + c) =
                make_float2(acc[i][j][0], acc[i][j][1]);
            *reinterpret_cast<float2*>(C + (size_t)(r0 + 8) * N + c) =
                make_float2(acc[i][j][2], acc[i][j][3]);
        }
    }
}

// ---------------------------------------------- reduce 4 partials -> bf16 hi/lo
__global__ void reduce4_split_kernel(const float* __restrict__ p,
                                     __nv_bfloat16* __restrict__ hi,
                                     __nv_bfloat16* __restrict__ lo) {
    const size_t i = (size_t)blockIdx.x * 256 + threadIdx.x;
    const size_t off = (size_t)OUT_D * D_FEAT / 4;
    const float4* pv = reinterpret_cast<const float4*>(p);
    float4 a = pv[i], b = pv[i + off], c = pv[i + 2 * off], d = pv[i + 3 * off];
    float4 s = make_float4((a.x + b.x) + (c.x + d.x), (a.y + b.y) + (c.y + d.y),
                           (a.z + b.z) + (c.z + d.z), (a.w + b.w) + (c.w + d.w));
    __nv_bfloat16 h0, l0, h1, l1, h2, l2, h3, l3;
    split_f32(s.x, h0, l0); split_f32(s.y, h1, l1);
    split_f32(s.z, h2, l2); split_f32(s.w, h3, l3);
    reinterpret_cast<ushort4*>(hi)[i] = make_ushort4(
        __bfloat16_as_ushort(h0), __bfloat16_as_ushort(h1),
        __bfloat16_as_ushort(h2), __bfloat16_as_ushort(h3));
    reinterpret_cast<ushort4*>(lo)[i] = make_ushort4(
        __bfloat16_as_ushort(l0), __bfloat16_as_ushort(l1),
        __bfloat16_as_ushort(l2), __bfloat16_as_ushort(l3));
}

// ---------------------------------------------- reduce 2 partials -> fp32 out
__global__ void reduce2_kernel(const float* __restrict__ p, float* __restrict__ out) {
    const size_t i = (size_t)blockIdx.x * 256 + threadIdx.x;
    const size_t off = (size_t)OUT_D * N_SAMP / 4;
    const float4* pv = reinterpret_cast<const float4*>(p);
    float4 a = pv[i], b = pv[i + off];
    reinterpret_cast<float4*>(out)[i] = make_float4(a.x + b.x, a.y + b.y, a.z + b.z, a.w + b.w);
}

// ---------------------------------------------------------------- launch
extern "C" void kernel_launch(void* const* d_in, const int* in_sizes, int n_in,
                              void* d_out, int out_size) {
    (void)n_in; (void)out_size;

    const float* x;
    const float* Psi;
    if (in_sizes[0] == D_FEAT * N_SAMP) {
        x   = (const float*)d_in[0];
        Psi = (const float*)d_in[1];
    } else {
        x   = (const float*)d_in[1];
        Psi = (const float*)d_in[0];
    }
    float* out = (float*)d_out;

    __nv_bfloat16 *psi_hi, *psi_lo, *x_hi, *x_lo, *tmp_hi, *tmp_lo;
    float *part1, *part2;
    cudaGetSymbolAddress((void**)&psi_hi, g_psi_hi);
    cudaGetSymbolAddress((void**)&psi_lo, g_psi_lo);
    cudaGetSymbolAddress((void**)&x_hi,   g_x_hi);
    cudaGetSymbolAddress((void**)&x_lo,   g_x_lo);
    cudaGetSymbolAddress((void**)&tmp_hi, g_tmp_hi);
    cudaGetSymbolAddress((void**)&tmp_lo, g_tmp_lo);
    cudaGetSymbolAddress((void**)&part1,  g_part1);
    cudaGetSymbolAddress((void**)&part2,  g_part2);

    const int SMEM_BYTES = 3 * STG_BYTES;   // 98304
    cudaFuncSetAttribute(gemm_hmma<0>, cudaFuncAttributeMaxDynamicSharedMemorySize, SMEM_BYTES);
    cudaFuncSetAttribute(gemm_hmma<1>, cudaFuncAttributeMaxDynamicSharedMemorySize, SMEM_BYTES);

    // 1) fused prep
    prep_kernel<<<OUT_D + XCHUNKS, 256>>>(Psi, x, psi_hi, psi_lo, x_hi, x_lo);

    // 2) GEMM1 split-K4 (B = x, non-trans)
    {
        dim3 grid(OUT_D / 128, D_FEAT / 128, 4);
        gemm_hmma<0><<<grid, 256, SMEM_BYTES>>>(
            psi_hi, psi_lo, x_hi, x_lo, part1, D_FEAT, N_SAMP, N_SAMP / 4, N_SAMP);
    }
    reduce4_split_kernel<<<(OUT_D * D_FEAT / 4) / 256, 256>>>(part1, tmp_hi, tmp_lo);

    // 3) GEMM2 split-K2 (B = x in [d,n] layout, trans ldsm)
    {
        dim3 grid(OUT_D / 128, N_SAMP / 128, 2);
        gemm_hmma<1><<<grid, 256, SMEM_BYTES>>>(
            tmp_hi, tmp_lo, x_hi, x_lo, part2, N_SAMP, D_FEAT, D_FEAT / 2, N_SAMP);
    }
    reduce2_kernel<<<(OUT_D * N_SAMP / 4) / 256, 256>>>(part2, out);
}